// round 1
// baseline (speedup 1.0000x reference)
#include <cuda_runtime.h>

// Problem constants (fixed by setup_inputs)
#define NF 1000
#define NB 2049
#define EPSV 1.1920928955078125e-07f   // float32 eps
#define SQEPS 3.45266983e-04f          // sqrt(eps)

#define WARPS 8
#define KF 8   // f-values per thread in reduction kernels

// Accumulators / tables (no cudaMalloc allowed)
__device__ float4 g_acc1[NB * 4];   // per (b,s): {sum|y0|^2, sum|y1|^2, Re sum y0 y1*, Im sum y0 y1*}
__device__ float4 g_acc2[NB * 4];
__device__ float4 g_Rn1[NB * 4];    // normalized R, iteration 1
__device__ float4 g_Rn2[NB * 4];    // normalized R, iteration 2

__global__ void k_zero() {
    int i = blockIdx.x * 256 + threadIdx.x;
    if (i < NB * 4) {
        g_acc1[i] = make_float4(0.f, 0.f, 0.f, 0.f);
        g_acc2[i] = make_float4(0.f, 0.f, 0.f, 0.f);
    }
}

// One EM update step for a single (f,b):
// inputs: channel signals i0,i1 (per s), normalized R table Rn[s], x vector xv.
// outputs: v[s] (E-step PSD of the INPUT) and filtered signals o0,o1.
__device__ __forceinline__ void em_step(
    const float i0r[4], const float i0i[4], const float i1r[4], const float i1i[4],
    const float4 Rn[4], const float4 xv,
    float v[4], float o0r[4], float o0i[4], float o1r[4], float o1i[4])
{
    float c00 = SQEPS, c11 = SQEPS, cre = 0.f, cim = 0.f;
#pragma unroll
    for (int s = 0; s < 4; s++) {
        v[s] = 0.5f * (i0r[s]*i0r[s] + i0i[s]*i0i[s] + i1r[s]*i1r[s] + i1i[s]*i1i[s]);
        c00 += v[s] * Rn[s].x;
        c11 += v[s] * Rn[s].y;
        cre += v[s] * Rn[s].z;
        cim += v[s] * Rn[s].w;
    }
    // Cxx is Hermitian: det real, >= eps thanks to sqrt(eps)*I regularizer
    float det = c00 * c11 - (cre * cre + cim * cim);
    float id = 1.0f / det;
    // w = Cxx^{-1} @ x,  Cxx^{-1} = id*[[c11, -c01],[-conj(c01), c00]]
    float w0r = id * (c11 * xv.x - (cre * xv.z - cim * xv.w));
    float w0i = id * (c11 * xv.y - (cre * xv.w + cim * xv.z));
    float w1r = id * (c00 * xv.z - (cre * xv.x + cim * xv.y));
    float w1i = id * (c00 * xv.w - (cre * xv.y - cim * xv.x));
#pragma unroll
    for (int s = 0; s < 4; s++) {
        // y0 = v*(R00*w0 + R01*w1),  y1 = v*(conj(R01)*w0 + R11*w1)
        o0r[s] = v[s] * (Rn[s].x * w0r + Rn[s].z * w1r - Rn[s].w * w1i);
        o0i[s] = v[s] * (Rn[s].x * w0i + Rn[s].z * w1i + Rn[s].w * w1r);
        o1r[s] = v[s] * (Rn[s].z * w0r + Rn[s].w * w0i + Rn[s].y * w1r);
        o1i[s] = v[s] * (Rn[s].z * w0i - Rn[s].w * w0r + Rn[s].y * w1i);
    }
}

// Block reduction over threadIdx.y (8 warps) + atomics into acc.
__device__ __forceinline__ void block_reduce_atomic(
    const float a00[4], const float a11[4], const float are[4], const float aim[4],
    int b, bool bok, float4* acc)
{
    __shared__ float red[WARPS][32][17];
    int lane = threadIdx.x, ty = threadIdx.y;
    float* p = red[ty][lane];
#pragma unroll
    for (int s = 0; s < 4; s++) {
        p[s]      = a00[s];
        p[4 + s]  = a11[s];
        p[8 + s]  = are[s];
        p[12 + s] = aim[s];
    }
    __syncthreads();
#pragma unroll
    for (int st = WARPS / 2; st >= 1; st >>= 1) {
        if (ty < st) {
            float* q = red[ty + st][lane];
#pragma unroll
            for (int i = 0; i < 16; i++) p[i] += q[i];
        }
        __syncthreads();
    }
    if (ty == 0 && bok) {
#pragma unroll
        for (int s = 0; s < 4; s++) {
            float* dst = ((float*)acc) + (b * 4 + s) * 4;
            atomicAdd(dst + 0, p[s]);
            atomicAdd(dst + 1, p[4 + s]);
            atomicAdd(dst + 2, p[8 + s]);
            atomicAdd(dst + 3, p[12 + s]);
        }
    }
}

// Pass 1: reduction over original y (forward f order)
__global__ void __launch_bounds__(256) k_red1(const float4* __restrict__ y)
{
    int lane = threadIdx.x;
    int b = blockIdx.x * 32 + lane;
    bool bok = b < NB;
    int f0 = blockIdx.y * (WARPS * KF) + threadIdx.y;

    float a00[4] = {0,0,0,0}, a11[4] = {0,0,0,0}, are[4] = {0,0,0,0}, aim[4] = {0,0,0,0};
    if (bok) {
#pragma unroll
        for (int k = 0; k < KF; k++) {
            int f = f0 + k * WARPS;
            if (f < NF) {
                const float4* py = y + (size_t)(f * NB + b) * 4;
                float4 q0 = py[0], q1 = py[1], q2 = py[2], q3 = py[3];
#define ACC_S(i, c0r, c0i, c1r, c1i)                  \
                a00[i] += c0r*c0r + c0i*c0i;          \
                a11[i] += c1r*c1r + c1i*c1i;          \
                are[i] += c0r*c1r + c0i*c1i;          \
                aim[i] += c0i*c1r - c0r*c1i;
                ACC_S(0, q0.x, q1.x, q2.x, q3.x)
                ACC_S(1, q0.y, q1.y, q2.y, q3.y)
                ACC_S(2, q0.z, q1.z, q2.z, q3.z)
                ACC_S(3, q0.w, q1.w, q2.w, q3.w)
#undef ACC_S
            }
        }
    }
    block_reduce_atomic(a00, a11, are, aim, b, bok, g_acc1);
}

__global__ void k_norm1() {
    int i = blockIdx.x * 256 + threadIdx.x;
    if (i >= NB * 4) return;
    float4 a = g_acc1[i];
    float inv = 1.0f / (EPSV + 0.5f * (a.x + a.y));
    g_Rn1[i] = make_float4(a.x * inv, a.y * inv, a.z * inv, a.w * inv);
}

// Pass 2: apply iteration-1 filter (recompute pointwise), reduce iteration-2 stats.
// Reversed f order to exploit L2 tail retention from pass 1.
__global__ void __launch_bounds__(256) k_iter(const float4* __restrict__ y,
                                              const float4* __restrict__ x)
{
    int lane = threadIdx.x;
    int b = blockIdx.x * 32 + lane;
    bool bok = b < NB;
    int byr = gridDim.y - 1 - blockIdx.y;
    int f0 = byr * (WARPS * KF) + threadIdx.y;

    float a00[4] = {0,0,0,0}, a11[4] = {0,0,0,0}, are[4] = {0,0,0,0}, aim[4] = {0,0,0,0};
    if (bok) {
        float4 Rn[4];
#pragma unroll
        for (int s = 0; s < 4; s++) Rn[s] = g_Rn1[b * 4 + s];
#pragma unroll
        for (int k = 0; k < KF; k++) {
            int f = f0 + k * WARPS;
            if (f < NF) {
                const float4* py = y + (size_t)(f * NB + b) * 4;
                float4 q0 = py[0], q1 = py[1], q2 = py[2], q3 = py[3];
                float4 xv = x[(size_t)(f * NB + b)];
                float i0r[4] = {q0.x, q0.y, q0.z, q0.w};
                float i0i[4] = {q1.x, q1.y, q1.z, q1.w};
                float i1r[4] = {q2.x, q2.y, q2.z, q2.w};
                float i1i[4] = {q3.x, q3.y, q3.z, q3.w};
                float v[4], o0r[4], o0i[4], o1r[4], o1i[4];
                em_step(i0r, i0i, i1r, i1i, Rn, xv, v, o0r, o0i, o1r, o1i);
#pragma unroll
                for (int s = 0; s < 4; s++) {
                    a00[s] += o0r[s]*o0r[s] + o0i[s]*o0i[s];
                    a11[s] += o1r[s]*o1r[s] + o1i[s]*o1i[s];
                    are[s] += o0r[s]*o1r[s] + o0i[s]*o1i[s];
                    aim[s] += o0i[s]*o1r[s] - o0r[s]*o1i[s];
                }
            }
        }
    }
    block_reduce_atomic(a00, a11, are, aim, b, bok, g_acc2);
}

// Normalize iteration-2 R and emit R_out (B, C, C, 2, S)
__global__ void k_norm2(float* __restrict__ rout) {
    int i = blockIdx.x * 256 + threadIdx.x;
    if (i >= NB * 4) return;
    float4 a = g_acc2[i];
    float inv = 1.0f / (EPSV + 0.5f * (a.x + a.y));
    float r00 = a.x * inv, r11 = a.y * inv, zr = a.z * inv, zi = a.w * inv;
    g_Rn2[i] = make_float4(r00, r11, zr, zi);
    int b = i >> 2, s = i & 3;
    float* p = rout + b * 32 + s;   // (((b*2+c)*2+d)*2+r)*4+s
    p[0]  = r00;  p[4]  = 0.f;      // R[0,0]
    p[8]  = zr;   p[12] = zi;       // R[0,1]
    p[16] = zr;   p[20] = -zi;      // R[1,0] = conj
    p[24] = r11;  p[28] = 0.f;      // R[1,1]
}

// Pass 3: recompute yc1, then apply iteration-2 filter; write v_out and y_out.
__global__ void __launch_bounds__(256) k_final(const float4* __restrict__ y,
                                               const float4* __restrict__ x,
                                               float4* __restrict__ yout,
                                               float4* __restrict__ vout)
{
    int lane = threadIdx.x;
    int b = blockIdx.x * 32 + lane;
    if (b >= NB) return;
    int f = blockIdx.y * WARPS + threadIdx.y;
    if (f >= NF) return;

    float4 Rn1[4], Rn2[4];
#pragma unroll
    for (int s = 0; s < 4; s++) { Rn1[s] = g_Rn1[b * 4 + s]; Rn2[s] = g_Rn2[b * 4 + s]; }

    const float4* py = y + (size_t)(f * NB + b) * 4;
    float4 q0 = py[0], q1 = py[1], q2 = py[2], q3 = py[3];
    float4 xv = x[(size_t)(f * NB + b)];

    float i0r[4] = {q0.x, q0.y, q0.z, q0.w};
    float i0i[4] = {q1.x, q1.y, q1.z, q1.w};
    float i1r[4] = {q2.x, q2.y, q2.z, q2.w};
    float i1i[4] = {q3.x, q3.y, q3.z, q3.w};

    float v1[4], m0r[4], m0i[4], m1r[4], m1i[4];
    em_step(i0r, i0i, i1r, i1i, Rn1, xv, v1, m0r, m0i, m1r, m1i);   // -> yc1

    float v2[4], p0r[4], p0i[4], p1r[4], p1i[4];
    em_step(m0r, m0i, m1r, m1i, Rn2, xv, v2, p0r, p0i, p1r, p1i);   // -> yc2, v2 = output v

    __stcs(vout + (size_t)(f * NB + b), make_float4(v2[0], v2[1], v2[2], v2[3]));

    float4* po = yout + (size_t)(f * NB + b) * 4;
    __stcs(po + 0, make_float4(p0r[0], p0r[1], p0r[2], p0r[3]));
    __stcs(po + 1, make_float4(p0i[0], p0i[1], p0i[2], p0i[3]));
    __stcs(po + 2, make_float4(p1r[0], p1r[1], p1r[2], p1r[3]));
    __stcs(po + 3, make_float4(p1i[0], p1i[1], p1i[2], p1i[3]));
}

extern "C" void kernel_launch(void* const* d_in, const int* in_sizes, int n_in,
                              void* d_out, int out_size)
{
    const float4* y = (const float4*)d_in[0];
    const float4* x = (const float4*)d_in[1];
    float* out = (float*)d_out;

    float4* yout = (float4*)out;                                   // (F,B,C,2,S)
    float4* vout = (float4*)(out + (size_t)NF * NB * 16);          // (F,B,S)
    float*  rout = out + (size_t)NF * NB * 16 + (size_t)NF * NB * 4; // (B,C,C,2,S)

    dim3 blk(32, WARPS);
    dim3 grd((NB + 31) / 32, (NF + WARPS * KF - 1) / (WARPS * KF));
    dim3 grd3((NB + 31) / 32, (NF + WARPS - 1) / WARPS);
    int nblk_small = (NB * 4 + 255) / 256;

    k_zero<<<nblk_small, 256>>>();
    k_red1<<<grd, blk>>>(y);
    k_norm1<<<nblk_small, 256>>>();
    k_iter<<<grd, blk>>>(y, x);
    k_norm2<<<nblk_small, 256>>>(rout);
    k_final<<<grd3, blk>>>(y, x, yout, vout);
}

// round 2
// speedup vs baseline: 1.2296x; 1.2296x over previous
#include <cuda_runtime.h>

// Problem constants (fixed by setup_inputs)
#define NF 1000
#define NB 2049
#define EPSV 1.1920928955078125e-07f   // float32 eps
#define SQEPS 3.45266983e-04f          // sqrt(eps)

#define WARPS 8
#define KF 8    // f-values per thread in reduction kernels
#define KF3 4   // f-values per thread in final kernel

// Accumulators / tables (no cudaMalloc allowed)
__device__ float4 g_acc1[NB * 4];   // per (b,s): {sum|y0|^2, sum|y1|^2, Re sum y0 y1*, Im sum y0 y1*}
__device__ float4 g_acc2[NB * 4];
__device__ float4 g_Rn1[NB * 4];    // normalized R, iteration 1
__device__ float4 g_Rn2[NB * 4];    // normalized R, iteration 2

__global__ void k_zero() {
    int i = blockIdx.x * 256 + threadIdx.x;
    if (i < NB * 4) {
        g_acc1[i] = make_float4(0.f, 0.f, 0.f, 0.f);
        g_acc2[i] = make_float4(0.f, 0.f, 0.f, 0.f);
    }
}

// One EM filter step for a single (f,b):
// inputs: channel signals i0,i1 (per s), normalized R table Rn[s], x vector xv.
// outputs: v[s] (E-step PSD of the INPUT) and filtered signals o0,o1.
__device__ __forceinline__ void em_step(
    const float i0r[4], const float i0i[4], const float i1r[4], const float i1i[4],
    const float4 Rn[4], const float4 xv,
    float v[4], float o0r[4], float o0i[4], float o1r[4], float o1i[4])
{
    float c00 = SQEPS, c11 = SQEPS, cre = 0.f, cim = 0.f;
#pragma unroll
    for (int s = 0; s < 4; s++) {
        v[s] = 0.5f * (i0r[s]*i0r[s] + i0i[s]*i0i[s] + i1r[s]*i1r[s] + i1i[s]*i1i[s]);
        c00 += v[s] * Rn[s].x;
        c11 += v[s] * Rn[s].y;
        cre += v[s] * Rn[s].z;
        cim += v[s] * Rn[s].w;
    }
    float det = c00 * c11 - (cre * cre + cim * cim);
    float id = 1.0f / det;
    float w0r = id * (c11 * xv.x - (cre * xv.z - cim * xv.w));
    float w0i = id * (c11 * xv.y - (cre * xv.w + cim * xv.z));
    float w1r = id * (c00 * xv.z - (cre * xv.x + cim * xv.y));
    float w1i = id * (c00 * xv.w - (cre * xv.y - cim * xv.x));
#pragma unroll
    for (int s = 0; s < 4; s++) {
        o0r[s] = v[s] * (Rn[s].x * w0r + Rn[s].z * w1r - Rn[s].w * w1i);
        o0i[s] = v[s] * (Rn[s].x * w0i + Rn[s].z * w1i + Rn[s].w * w1r);
        o1r[s] = v[s] * (Rn[s].z * w0r + Rn[s].w * w0i + Rn[s].y * w1r);
        o1i[s] = v[s] * (Rn[s].z * w0i - Rn[s].w * w0r + Rn[s].y * w1i);
    }
}

// Block reduction over threadIdx.y (8 warps) + atomics into acc.
__device__ __forceinline__ void block_reduce_atomic(
    const float a00[4], const float a11[4], const float are[4], const float aim[4],
    int b, bool bok, float4* acc)
{
    __shared__ float red[WARPS][32][17];
    int lane = threadIdx.x, ty = threadIdx.y;
    float* p = red[ty][lane];
#pragma unroll
    for (int s = 0; s < 4; s++) {
        p[s]      = a00[s];
        p[4 + s]  = a11[s];
        p[8 + s]  = are[s];
        p[12 + s] = aim[s];
    }
    __syncthreads();
#pragma unroll
    for (int st = WARPS / 2; st >= 1; st >>= 1) {
        if (ty < st) {
            float* q = red[ty + st][lane];
#pragma unroll
            for (int i = 0; i < 16; i++) p[i] += q[i];
        }
        __syncthreads();
    }
    if (ty == 0 && bok) {
#pragma unroll
        for (int s = 0; s < 4; s++) {
            float* dst = ((float*)acc) + (b * 4 + s) * 4;
            atomicAdd(dst + 0, p[s]);
            atomicAdd(dst + 1, p[4 + s]);
            atomicAdd(dst + 2, p[8 + s]);
            atomicAdd(dst + 3, p[12 + s]);
        }
    }
}

// Pass 1: reduction over original y (forward f order)
__global__ void __launch_bounds__(256) k_red1(const float4* __restrict__ y)
{
    int lane = threadIdx.x;
    int b = blockIdx.x * 32 + lane;
    bool bok = b < NB;
    int f0 = blockIdx.y * (WARPS * KF) + threadIdx.y;

    float a00[4] = {0,0,0,0}, a11[4] = {0,0,0,0}, are[4] = {0,0,0,0}, aim[4] = {0,0,0,0};
    if (bok) {
#pragma unroll
        for (int k = 0; k < KF; k++) {
            int f = f0 + k * WARPS;
            if (f < NF) {
                const float4* py = y + (size_t)(f * NB + b) * 4;
                float4 q0 = py[0], q1 = py[1], q2 = py[2], q3 = py[3];
#define ACC_S(i, c0r, c0i, c1r, c1i)                  \
                a00[i] += c0r*c0r + c0i*c0i;          \
                a11[i] += c1r*c1r + c1i*c1i;          \
                are[i] += c0r*c1r + c0i*c1i;          \
                aim[i] += c0i*c1r - c0r*c1i;
                ACC_S(0, q0.x, q1.x, q2.x, q3.x)
                ACC_S(1, q0.y, q1.y, q2.y, q3.y)
                ACC_S(2, q0.z, q1.z, q2.z, q3.z)
                ACC_S(3, q0.w, q1.w, q2.w, q3.w)
#undef ACC_S
            }
        }
    }
    block_reduce_atomic(a00, a11, are, aim, b, bok, g_acc1);
}

__global__ void k_norm1() {
    int i = blockIdx.x * 256 + threadIdx.x;
    if (i >= NB * 4) return;
    float4 a = g_acc1[i];
    float inv = 1.0f / (EPSV + 0.5f * (a.x + a.y));
    g_Rn1[i] = make_float4(a.x * inv, a.y * inv, a.z * inv, a.w * inv);
}

// Pass 2: apply iteration-1 filter (recompute pointwise), reduce iteration-2 stats,
// and write v_out = mean-channel PSD of yc1 (this is the returned v AND all that
// pass 3 needs besides x). Reversed f order for L2 tail retention from pass 1.
__global__ void __launch_bounds__(256) k_iter(const float4* __restrict__ y,
                                              const float4* __restrict__ x,
                                              float4* __restrict__ vout)
{
    int lane = threadIdx.x;
    int b = blockIdx.x * 32 + lane;
    bool bok = b < NB;
    int byr = gridDim.y - 1 - blockIdx.y;
    int f0 = byr * (WARPS * KF) + threadIdx.y;

    float a00[4] = {0,0,0,0}, a11[4] = {0,0,0,0}, are[4] = {0,0,0,0}, aim[4] = {0,0,0,0};
    if (bok) {
        float4 Rn[4];
#pragma unroll
        for (int s = 0; s < 4; s++) Rn[s] = g_Rn1[b * 4 + s];
#pragma unroll
        for (int k = 0; k < KF; k++) {
            int f = f0 + k * WARPS;
            if (f < NF) {
                const float4* py = y + (size_t)(f * NB + b) * 4;
                float4 q0 = py[0], q1 = py[1], q2 = py[2], q3 = py[3];
                float4 xv = x[(size_t)(f * NB + b)];
                float i0r[4] = {q0.x, q0.y, q0.z, q0.w};
                float i0i[4] = {q1.x, q1.y, q1.z, q1.w};
                float i1r[4] = {q2.x, q2.y, q2.z, q2.w};
                float i1i[4] = {q3.x, q3.y, q3.z, q3.w};
                float v[4], o0r[4], o0i[4], o1r[4], o1i[4];
                em_step(i0r, i0i, i1r, i1i, Rn, xv, v, o0r, o0i, o1r, o1i);
                float v2[4];
#pragma unroll
                for (int s = 0; s < 4; s++) {
                    float t00 = o0r[s]*o0r[s] + o0i[s]*o0i[s];
                    float t11 = o1r[s]*o1r[s] + o1i[s]*o1i[s];
                    a00[s] += t00;
                    a11[s] += t11;
                    are[s] += o0r[s]*o1r[s] + o0i[s]*o1i[s];
                    aim[s] += o0i[s]*o1r[s] - o0r[s]*o1i[s];
                    v2[s] = 0.5f * (t00 + t11);
                }
                __stcs(vout + (size_t)(f * NB + b),
                       make_float4(v2[0], v2[1], v2[2], v2[3]));
            }
        }
    }
    block_reduce_atomic(a00, a11, are, aim, b, bok, g_acc2);
}

// Normalize iteration-2 R and emit R_out (B, C, C, 2, S)
__global__ void k_norm2(float* __restrict__ rout) {
    int i = blockIdx.x * 256 + threadIdx.x;
    if (i >= NB * 4) return;
    float4 a = g_acc2[i];
    float inv = 1.0f / (EPSV + 0.5f * (a.x + a.y));
    float r00 = a.x * inv, r11 = a.y * inv, zr = a.z * inv, zi = a.w * inv;
    g_Rn2[i] = make_float4(r00, r11, zr, zi);
    int b = i >> 2, s = i & 3;
    float* p = rout + b * 32 + s;   // (((b*2+c)*2+d)*2+r)*4+s
    p[0]  = r00;  p[4]  = 0.f;      // R[0,0]
    p[8]  = zr;   p[12] = zi;       // R[0,1]
    p[16] = zr;   p[20] = -zi;      // R[1,0] = conj
    p[24] = r11;  p[28] = 0.f;      // R[1,1]
}

// Pass 3: read v2 (written by pass 2) + x, build the iteration-2 Wiener filter,
// write y_out. No y re-read, no yc1 recompute.
__global__ void __launch_bounds__(256) k_final(const float4* __restrict__ vin,
                                               const float4* __restrict__ x,
                                               float4* __restrict__ yout)
{
    int lane = threadIdx.x;
    int b = blockIdx.x * 32 + lane;
    if (b >= NB) return;

    float4 Rn[4];
#pragma unroll
    for (int s = 0; s < 4; s++) Rn[s] = g_Rn2[b * 4 + s];

    int f0 = blockIdx.y * (WARPS * KF3) + threadIdx.y;
#pragma unroll
    for (int k = 0; k < KF3; k++) {
        int f = f0 + k * WARPS;
        if (f >= NF) continue;
        size_t p = (size_t)f * NB + b;
        float4 vv = __ldcs(vin + p);
        float4 xv = x[p];
        float va[4] = {vv.x, vv.y, vv.z, vv.w};

        float c00 = SQEPS, c11 = SQEPS, cre = 0.f, cim = 0.f;
#pragma unroll
        for (int s = 0; s < 4; s++) {
            c00 += va[s] * Rn[s].x;
            c11 += va[s] * Rn[s].y;
            cre += va[s] * Rn[s].z;
            cim += va[s] * Rn[s].w;
        }
        float det = c00 * c11 - (cre * cre + cim * cim);
        float id = 1.0f / det;
        float w0r = id * (c11 * xv.x - (cre * xv.z - cim * xv.w));
        float w0i = id * (c11 * xv.y - (cre * xv.w + cim * xv.z));
        float w1r = id * (c00 * xv.z - (cre * xv.x + cim * xv.y));
        float w1i = id * (c00 * xv.w - (cre * xv.y - cim * xv.x));

        float o0r[4], o0i[4], o1r[4], o1i[4];
#pragma unroll
        for (int s = 0; s < 4; s++) {
            o0r[s] = va[s] * (Rn[s].x * w0r + Rn[s].z * w1r - Rn[s].w * w1i);
            o0i[s] = va[s] * (Rn[s].x * w0i + Rn[s].z * w1i + Rn[s].w * w1r);
            o1r[s] = va[s] * (Rn[s].z * w0r + Rn[s].w * w0i + Rn[s].y * w1r);
            o1i[s] = va[s] * (Rn[s].z * w0i - Rn[s].w * w0r + Rn[s].y * w1i);
        }

        float4* po = yout + p * 4;
        __stcs(po + 0, make_float4(o0r[0], o0r[1], o0r[2], o0r[3]));
        __stcs(po + 1, make_float4(o0i[0], o0i[1], o0i[2], o0i[3]));
        __stcs(po + 2, make_float4(o1r[0], o1r[1], o1r[2], o1r[3]));
        __stcs(po + 3, make_float4(o1i[0], o1i[1], o1i[2], o1i[3]));
    }
}

extern "C" void kernel_launch(void* const* d_in, const int* in_sizes, int n_in,
                              void* d_out, int out_size)
{
    const float4* y = (const float4*)d_in[0];
    const float4* x = (const float4*)d_in[1];
    float* out = (float*)d_out;

    float4* yout = (float4*)out;                                     // (F,B,C,2,S)
    float4* vout = (float4*)(out + (size_t)NF * NB * 16);            // (F,B,S)
    float*  rout = out + (size_t)NF * NB * 16 + (size_t)NF * NB * 4; // (B,C,C,2,S)

    dim3 blk(32, WARPS);
    dim3 grd((NB + 31) / 32, (NF + WARPS * KF - 1) / (WARPS * KF));
    dim3 grd3((NB + 31) / 32, (NF + WARPS * KF3 - 1) / (WARPS * KF3));
    int nblk_small = (NB * 4 + 255) / 256;

    k_zero<<<nblk_small, 256>>>();
    k_red1<<<grd, blk>>>(y);
    k_norm1<<<nblk_small, 256>>>();
    k_iter<<<grd, blk>>>(y, x, vout);
    k_norm2<<<nblk_small, 256>>>(rout);
    k_final<<<grd3, blk>>>(vout, x, yout);
}